// round 15
// baseline (speedup 1.0000x reference)
#include <cuda_runtime.h>
#include <cuda_bf16.h>
#include <cuda_fp16.h>
#include <mma.h>
#include <math.h>

using namespace nvcuda;

#define USER_NUM 100000
#define ITEM_NUM 50000
#define NN 150000
#define NE 2400000
#define NBATCH 4096
#define SCAN_B ((NN + 255) / 256)   // 586

// Scratch (device globals; allocation is forbidden).
__device__ uint4 g_x16raw[150016 * 128 / 8];   // x·dis fp16 (GEMM A / layer input)
__device__ uint4 g_h16raw[150016 * 128 / 8];   // GEMM output h / layer-0 aggregated xs
__device__ uint4 g_w16raw[3 * 128 * 128 / 8];  // W0|W1|W2 fp16
#define G_X16 (reinterpret_cast<__half*>(g_x16raw))
#define G_H16 (reinterpret_cast<__half*>(g_h16raw))
#define G_W16 (reinterpret_cast<__half*>(g_w16raw))
__device__ uint2 g_a16raw[150016 * 128 / 4];   // conv output (pre-BN), fp16
#define G_A16 (reinterpret_cast<__half*>(g_a16raw))
__device__ float g_dis[150016];                // rsqrt(1+deg)
__device__ int   g_degi[150016];
__device__ int   g_rows[150016 + 16];          // CSR row offsets (by dst)
__device__ int   g_cursor[150016];
__device__ int   g_part[1024];
__device__ int   g_csrc[NE];                   // CSR column (src) ids
__device__ float g_stats[1024];                // L0: sum@0 sq@128 | L1: sum@512 sq@640
__device__ float g_loss;

// ---------------- setup ----------------

__global__ void k_zero() {
    int i = blockIdx.x * 256 + threadIdx.x;
    if (i < NN) g_degi[i] = 0;
    if (i < 256) { g_stats[i] = 0.f; g_stats[512 + i] = 0.f; }
    if (i == 0) g_loss = 0.f;
}

__global__ void k_deg(const int* __restrict__ dst) {
    int i = blockIdx.x * 256 + threadIdx.x;
    if (i >= NE / 4) return;
    int4 d = ((const int4*)dst)[i];
    atomicAdd(&g_degi[d.x], 1);
    atomicAdd(&g_degi[d.y], 1);
    atomicAdd(&g_degi[d.z], 1);
    atomicAdd(&g_degi[d.w], 1);
}

__global__ void k_dis() {
    int i = blockIdx.x * 256 + threadIdx.x;
    if (i < NN) g_dis[i] = rsqrtf(1.f + (float)g_degi[i]);
}

__global__ void k_concat16(const float* __restrict__ ue, const float* __restrict__ ie) {
    int i = blockIdx.x * 256 + threadIdx.x;
    const int TT = NN * 8;
    if (i >= TT) return;
    int row = i >> 3;
    int col = (i & 7) * 8;
    float d = g_dis[row];
    const float* srcp = (row < USER_NUM) ? ue + (size_t)row * 64 + col
                                         : ie + (size_t)(row - USER_NUM) * 64 + col;
    float4 v0 = *(const float4*)srcp;
    float4 v1 = *(const float4*)(srcp + 4);
    __align__(16) __half2 h[4];
    h[0] = __floats2half2_rn(v0.x * d, v0.y * d);
    h[1] = __floats2half2_rn(v0.z * d, v0.w * d);
    h[2] = __floats2half2_rn(v1.x * d, v1.y * d);
    h[3] = __floats2half2_rn(v1.z * d, v1.w * d);
    *reinterpret_cast<uint4*>(G_X16 + (size_t)row * 64 + col) =
        *reinterpret_cast<const uint4*>(h);
}

__global__ void k_wconv(const float* __restrict__ W, int kn4, int woff) {
    int i = blockIdx.x * 256 + threadIdx.x;
    if (i >= kn4) return;
    float4 v = ((const float4*)W)[i];
    __align__(8) __half2 h[2];
    h[0] = __floats2half2_rn(v.x, v.y);
    h[1] = __floats2half2_rn(v.z, v.w);
    *reinterpret_cast<uint2*>(G_W16 + woff + i * 4) = *reinterpret_cast<const uint2*>(h);
}

// ---------------- prefix scan ----------------

__global__ void k_scan1() {
    __shared__ int s[256];
    int tid = threadIdx.x;
    int i = blockIdx.x * 256 + tid;
    int v = (i < NN) ? g_degi[i] : 0;
    s[tid] = v;
    __syncthreads();
    for (int off = 1; off < 256; off <<= 1) {
        int t = (tid >= off) ? s[tid - off] : 0;
        __syncthreads();
        s[tid] += t;
        __syncthreads();
    }
    if (i < NN) g_rows[i] = s[tid] - v;
    if (tid == 255) g_part[blockIdx.x] = s[255];
}

__global__ void k_scan2() {  // 1 block, 1024 threads
    __shared__ int s[1024];
    int tid = threadIdx.x;
    int v = (tid < SCAN_B) ? g_part[tid] : 0;
    s[tid] = v;
    __syncthreads();
    for (int off = 1; off < 1024; off <<= 1) {
        int t = (tid >= off) ? s[tid - off] : 0;
        __syncthreads();
        s[tid] += t;
        __syncthreads();
    }
    if (tid < SCAN_B) g_part[tid] = s[tid] - v;
}

__global__ void k_scan3() {
    int i = blockIdx.x * 256 + threadIdx.x;
    if (i < NN) {
        int r = g_rows[i] + g_part[i >> 8];
        g_rows[i] = r;
        g_cursor[i] = r;
    }
    if (i == NN) g_rows[NN] = NE;
}

__global__ void k_csrfill(const int* __restrict__ src, const int* __restrict__ dst) {
    int i = blockIdx.x * 256 + threadIdx.x;
    if (i >= NE / 4) return;
    int4 s = ((const int4*)src)[i];
    int4 d = ((const int4*)dst)[i];
    g_csrc[atomicAdd(&g_cursor[d.x], 1)] = s.x;
    g_csrc[atomicAdd(&g_cursor[d.y], 1)] = s.y;
    g_csrc[atomicAdd(&g_cursor[d.z], 1)] = s.z;
    g_csrc[atomicAdd(&g_cursor[d.w], 1)] = s.w;
}

// ---------------- layer-0 pre-GEMM aggregation in x-space (64-wide) ------------
// ax[n] = dis[n]*(xs[n] + sum_{e->n} xs[src]); xs = x·dis in G_X16. Out: G_H16 fp16.
__global__ __launch_bounds__(256) void k_aggx64() {
    const int lane = threadIdx.x & 31;
    const int warp = threadIdx.x >> 5;
    for (int node = blockIdx.x * 8 + warp; node < NN; node += gridDim.x * 8) {
        float a0, a1;
        {
            unsigned raw = *(const unsigned*)(G_X16 + (size_t)node * 64 + lane * 2);
            float2 f = __half22float2(*reinterpret_cast<__half2*>(&raw));
            a0 = f.x; a1 = f.y;
        }
        int beg = g_rows[node], end = g_rows[node + 1];
        int e = beg;
        for (; e + 8 <= end; e += 8) {
            int sid[8];
#pragma unroll
            for (int u = 0; u < 8; u++) sid[u] = g_csrc[e + u];
            unsigned r[8];
#pragma unroll
            for (int u = 0; u < 8; u++)
                r[u] = *(const unsigned*)(G_X16 + (size_t)sid[u] * 64 + lane * 2);
#pragma unroll
            for (int u = 0; u < 8; u++) {
                float2 f = __half22float2(*reinterpret_cast<__half2*>(&r[u]));
                a0 += f.x; a1 += f.y;
            }
        }
        for (; e < end; e++) {
            int s0 = g_csrc[e];
            unsigned r0 = *(const unsigned*)(G_X16 + (size_t)s0 * 64 + lane * 2);
            float2 f = __half22float2(*reinterpret_cast<__half2*>(&r0));
            a0 += f.x; a1 += f.y;
        }
        float dd = g_dis[node];
        __half2 h = __floats2half2_rn(a0 * dd, a1 * dd);
        *reinterpret_cast<unsigned*>(G_H16 + (size_t)node * 64 + lane * 2) =
            *reinterpret_cast<const unsigned*>(&h);
    }
}

// ---------------- tensor-core GEMM: g_h16 = g_x16 @ W16 (plain) ----------------
template <int K, int N>
__global__ __launch_bounds__(256) void k_gemmh(int woff) {
    __shared__ __half Ws[K * N];
    __shared__ float scr[8][256];
    const int tid = threadIdx.x;
    const int wid = tid >> 5;
    const int lane = tid & 31;

    for (int i = tid; i < K * N / 8; i += 256)
        ((uint4*)Ws)[i] = ((const uint4*)(G_W16 + woff))[i];
    __syncthreads();

    const size_t rowbase = (size_t)blockIdx.x * 128 + wid * 16;
    const __half* A = G_X16 + rowbase * K;

    wmma::fragment<wmma::accumulator, 16, 16, 16, float> acc[N / 16];
#pragma unroll
    for (int j = 0; j < N / 16; j++) wmma::fill_fragment(acc[j], 0.f);

#pragma unroll
    for (int k0 = 0; k0 < K / 16; k0++) {
        wmma::fragment<wmma::matrix_a, 16, 16, 16, __half, wmma::row_major> a;
        wmma::load_matrix_sync(a, A + k0 * 16, K);
#pragma unroll
        for (int j = 0; j < N / 16; j++) {
            wmma::fragment<wmma::matrix_b, 16, 16, 16, __half, wmma::row_major> b;
            wmma::load_matrix_sync(b, Ws + k0 * 16 * N + j * 16, N);
            wmma::mma_sync(acc[j], a, b, acc[j]);
        }
    }

    __half* H = G_H16 + rowbase * N;
    const int r = lane >> 1;
    const int c0 = (lane & 1) * 8;
#pragma unroll
    for (int j = 0; j < N / 16; j++) {
        wmma::store_matrix_sync(scr[wid], acc[j], 16, wmma::mem_row_major);
        __syncwarp();
        __align__(16) __half2 h[4];
#pragma unroll
        for (int t = 0; t < 4; t++)
            h[t] = __floats2half2_rn(scr[wid][r * 16 + c0 + 2 * t],
                                     scr[wid][r * 16 + c0 + 2 * t + 1]);
        *reinterpret_cast<uint4*>(H + (size_t)r * N + j * 16 + c0) =
            *reinterpret_cast<const uint4*>(h);
        __syncwarp();
    }
}

// ---- layer-0 GEMM: A = aggregated xs (G_H16, 64-wide); out = A@W0 + b0 -> G_A16,
//      with fused BN column stats (masked for tail rows >= NN). ----
__global__ __launch_bounds__(256) void k_gemm0stats(int woff, const float* __restrict__ b) {
    constexpr int K = 64, N = 128;
    __shared__ __half Ws[K * N];
    __shared__ float scr[8][256];
    __shared__ float b_s[128], s_sum[128], s_sq[128];
    const int tid = threadIdx.x;
    const int wid = tid >> 5;
    const int lane = tid & 31;

    if (tid < 128) { b_s[tid] = b[tid]; s_sum[tid] = 0.f; s_sq[tid] = 0.f; }
    for (int i = tid; i < K * N / 8; i += 256)
        ((uint4*)Ws)[i] = ((const uint4*)(G_W16 + woff))[i];
    __syncthreads();

    const size_t rowbase = (size_t)blockIdx.x * 128 + wid * 16;
    const __half* A = G_H16 + rowbase * K;

    wmma::fragment<wmma::accumulator, 16, 16, 16, float> acc[N / 16];
#pragma unroll
    for (int j = 0; j < N / 16; j++) wmma::fill_fragment(acc[j], 0.f);

#pragma unroll
    for (int k0 = 0; k0 < K / 16; k0++) {
        wmma::fragment<wmma::matrix_a, 16, 16, 16, __half, wmma::row_major> a;
        wmma::load_matrix_sync(a, A + k0 * 16, K);
#pragma unroll
        for (int j = 0; j < N / 16; j++) {
            wmma::fragment<wmma::matrix_b, 16, 16, 16, __half, wmma::row_major> b_;
            wmma::load_matrix_sync(b_, Ws + k0 * 16 * N + j * 16, N);
            wmma::mma_sync(acc[j], a, b_, acc[j]);
        }
    }

    const int r = lane >> 1;
    const int c0 = (lane & 1) * 8;
    const bool valid = (int)rowbase + r < NN;
    __half* Aout = G_A16 + rowbase * 128;
#pragma unroll
    for (int j = 0; j < N / 16; j++) {
        wmma::store_matrix_sync(scr[wid], acc[j], 16, wmma::mem_row_major);
        __syncwarp();
        float v[8];
#pragma unroll
        for (int t = 0; t < 8; t++)
            v[t] = valid ? (scr[wid][r * 16 + c0 + t] + b_s[j * 16 + c0 + t]) : 0.f;
        if (valid) {
            __align__(16) __half2 h[4];
#pragma unroll
            for (int t = 0; t < 4; t++)
                h[t] = __floats2half2_rn(v[2 * t], v[2 * t + 1]);
            *reinterpret_cast<uint4*>(Aout + (size_t)r * 128 + j * 16 + c0) =
                *reinterpret_cast<const uint4*>(h);
        }
        float sums[8], sqs[8];
#pragma unroll
        for (int t = 0; t < 8; t++) { sums[t] = v[t]; sqs[t] = v[t] * v[t]; }
#pragma unroll
        for (int off = 2; off <= 16; off <<= 1) {
#pragma unroll
            for (int t = 0; t < 8; t++) {
                sums[t] += __shfl_xor_sync(0xffffffffu, sums[t], off);
                sqs[t]  += __shfl_xor_sync(0xffffffffu, sqs[t], off);
            }
        }
        if (lane < 2) {
#pragma unroll
            for (int t = 0; t < 8; t++) {
                atomicAdd(&s_sum[j * 16 + c0 + t], sums[t]);
                atomicAdd(&s_sq[j * 16 + c0 + t], sqs[t]);
            }
        }
        __syncwarp();
    }
    __syncthreads();
    if (tid < 128) {
        atomicAdd(&g_stats[tid], s_sum[tid]);
        atomicAdd(&g_stats[128 + tid], s_sq[tid]);
    }
}

// ---------------- CSR aggregation (warp-per-node, U=8) -------------------------
template <int N, bool FINAL>
__global__ __launch_bounds__(256) void k_agg(const float* __restrict__ b,
                                             float* __restrict__ out, int sbase) {
    constexpr int VE = N / 32;
    const int lane = threadIdx.x & 31;
    const int warp = threadIdx.x >> 5;
    __shared__ float s_sum[128], s_sq[128];
    if constexpr (!FINAL) {
        if (threadIdx.x < 128) { s_sum[threadIdx.x] = 0.f; s_sq[threadIdx.x] = 0.f; }
        __syncthreads();
    }
    float bv[VE], tsum[VE], tsq[VE];
#pragma unroll
    for (int i = 0; i < VE; i++) { bv[i] = b[lane * VE + i]; tsum[i] = 0.f; tsq[i] = 0.f; }

    for (int node = blockIdx.x * 8 + warp; node < NN; node += gridDim.x * 8) {
        float acc[VE];
        if constexpr (VE == 4) {
            uint2 raw = *(const uint2*)(G_H16 + (size_t)node * N + lane * 4);
            float2 f0 = __half22float2(*reinterpret_cast<__half2*>(&raw.x));
            float2 f1 = __half22float2(*reinterpret_cast<__half2*>(&raw.y));
            acc[0] = f0.x; acc[1] = f0.y; acc[2] = f1.x; acc[3] = f1.y;
        } else {
            unsigned raw = *(const unsigned*)(G_H16 + (size_t)node * N + lane * 2);
            float2 f = __half22float2(*reinterpret_cast<__half2*>(&raw));
            acc[0] = f.x; acc[1] = f.y;
        }
        int beg = g_rows[node], end = g_rows[node + 1];
        int e = beg;
        for (; e + 8 <= end; e += 8) {
            int sid[8];
#pragma unroll
            for (int u = 0; u < 8; u++) sid[u] = g_csrc[e + u];
            if constexpr (VE == 4) {
                uint2 r[8];
#pragma unroll
                for (int u = 0; u < 8; u++)
                    r[u] = *(const uint2*)(G_H16 + (size_t)sid[u] * N + lane * 4);
#pragma unroll
                for (int u = 0; u < 8; u++) {
                    float2 f0 = __half22float2(*reinterpret_cast<__half2*>(&r[u].x));
                    float2 f1 = __half22float2(*reinterpret_cast<__half2*>(&r[u].y));
                    acc[0] += f0.x; acc[1] += f0.y; acc[2] += f1.x; acc[3] += f1.y;
                }
            } else {
                unsigned r[8];
#pragma unroll
                for (int u = 0; u < 8; u++)
                    r[u] = *(const unsigned*)(G_H16 + (size_t)sid[u] * N + lane * 2);
#pragma unroll
                for (int u = 0; u < 8; u++) {
                    float2 f = __half22float2(*reinterpret_cast<__half2*>(&r[u]));
                    acc[0] += f.x; acc[1] += f.y;
                }
            }
        }
        for (; e < end; e++) {
            int s0 = g_csrc[e];
            if constexpr (VE == 4) {
                uint2 r0 = *(const uint2*)(G_H16 + (size_t)s0 * N + lane * 4);
                float2 f0 = __half22float2(*reinterpret_cast<__half2*>(&r0.x));
                float2 f1 = __half22float2(*reinterpret_cast<__half2*>(&r0.y));
                acc[0] += f0.x; acc[1] += f0.y; acc[2] += f1.x; acc[3] += f1.y;
            } else {
                unsigned r0 = *(const unsigned*)(G_H16 + (size_t)s0 * N + lane * 2);
                float2 f = __half22float2(*reinterpret_cast<__half2*>(&r0));
                acc[0] += f.x; acc[1] += f.y;
            }
        }
        float dd = g_dis[node];
        float v[VE];
#pragma unroll
        for (int i = 0; i < VE; i++) {
            v[i] = fmaf(acc[i], dd, bv[i]);
            if constexpr (!FINAL) { tsum[i] += v[i]; tsq[i] += v[i] * v[i]; }
        }

        if constexpr (FINAL) {
            float* orow = out + (size_t)node * N + lane * VE;
#pragma unroll
            for (int i = 0; i < VE; i++) orow[i] = v[i];
        } else {
            __align__(8) __half2 h[2];
            h[0] = __floats2half2_rn(v[0], v[1]);
            h[1] = __floats2half2_rn(v[2], v[3]);
            *reinterpret_cast<uint2*>(G_A16 + (size_t)node * 128 + lane * 4) =
                *reinterpret_cast<const uint2*>(h);
        }
    }

    if constexpr (!FINAL) {
#pragma unroll
        for (int i = 0; i < VE; i++) {
            atomicAdd(&s_sum[lane * VE + i], tsum[i]);
            atomicAdd(&s_sq[lane * VE + i], tsq[i]);
        }
        __syncthreads();
        if (threadIdx.x < 128) {
            atomicAdd(&g_stats[sbase + threadIdx.x], s_sum[threadIdx.x]);
            atomicAdd(&g_stats[sbase + 128 + threadIdx.x], s_sq[threadIdx.x]);
        }
    }
}

// ---------------- BN apply + ReLU + L2 + fp16 (reads G_A16) --------------------
__global__ __launch_bounds__(256) void k_bnapply(const float* __restrict__ g,
                                                 const float* __restrict__ beta,
                                                 int sbase) {
    __shared__ float s_sc[128], s_sh[128];
    if (threadIdx.x < 128) {
        int c = threadIdx.x;
        float m = g_stats[sbase + c] * (1.f / NN);
        float var = g_stats[sbase + 128 + c] * (1.f / NN) - m * m;
        float sc = g[c] * rsqrtf(var + 1e-5f);
        s_sc[c] = sc;
        s_sh[c] = beta[c] - m * sc;
    }
    __syncthreads();
    int row = blockIdx.x * 8 + (threadIdx.x >> 5);
    int lane = threadIdx.x & 31;
    if (row >= NN) return;
    uint2 raw = *reinterpret_cast<const uint2*>(G_A16 + (size_t)row * 128 + lane * 4);
    float2 f0 = __half22float2(*reinterpret_cast<__half2*>(&raw.x));
    float2 f1 = __half22float2(*reinterpret_cast<__half2*>(&raw.y));
    float4 sc = *reinterpret_cast<const float4*>(s_sc + lane * 4);
    float4 sh = *reinterpret_cast<const float4*>(s_sh + lane * 4);
    float y0 = fmaxf(fmaf(f0.x, sc.x, sh.x), 0.f);
    float y1 = fmaxf(fmaf(f0.y, sc.y, sh.y), 0.f);
    float y2 = fmaxf(fmaf(f1.x, sc.z, sh.z), 0.f);
    float y3 = fmaxf(fmaf(f1.y, sc.w, sh.w), 0.f);
    float sq = y0 * y0 + y1 * y1 + y2 * y2 + y3 * y3;
#pragma unroll
    for (int o = 16; o; o >>= 1) sq += __shfl_xor_sync(0xffffffffu, sq, o);
    float inv = 1.f / fmaxf(sqrtf(sq), 1e-12f);
    inv *= g_dis[row];  // pre-scale for next GEMM
    __align__(8) __half2 h[2];
    h[0] = __floats2half2_rn(y0 * inv, y1 * inv);
    h[1] = __floats2half2_rn(y2 * inv, y3 * inv);
    *reinterpret_cast<uint2*>(G_X16 + (size_t)row * 128 + lane * 4) =
        *reinterpret_cast<const uint2*>(h);
}

// ---------------- BPR loss ----------------
__global__ __launch_bounds__(256) void k_loss(const float* __restrict__ xo,
                                              const int* __restrict__ uid,
                                              const int* __restrict__ pid,
                                              const int* __restrict__ nid) {
    int s = blockIdx.x * 8 + (threadIdx.x >> 5);
    int lane = threadIdx.x & 31;
    if (s >= NBATCH) return;
    const float* u = xo + (size_t)uid[s] * 64;
    const float* p = xo + (size_t)(USER_NUM + pid[s]) * 64;
    const float* nr = xo + (size_t)(USER_NUM + nid[s]) * 64;
    float ps = 0.f, ns = 0.f;
#pragma unroll
    for (int j = 0; j < 2; j++) {
        int c = lane + j * 32;
        float uv = u[c];
        ps += uv * p[c];
        ns += uv * nr[c];
    }
#pragma unroll
    for (int o = 16; o; o >>= 1) {
        ps += __shfl_xor_sync(0xffffffffu, ps, o);
        ns += __shfl_xor_sync(0xffffffffu, ns, o);
    }
    if (lane == 0) {
        float z = ps - ns;
        float ls = fminf(z, 0.f) - log1pf(expf(-fabsf(z)));
        atomicAdd(&g_loss, ls);
    }
}

__global__ void k_wloss(float* __restrict__ out) {
    out[0] = -g_loss * (1.f / NBATCH);
}

// ---------------- launch ----------------
extern "C" void kernel_launch(void* const* d_in, const int* in_sizes, int n_in,
                              void* d_out, int out_size) {
    const float* user_emb = (const float*)d_in[0];
    const float* item_emb = (const float*)d_in[1];
    const float* W0 = (const float*)d_in[2];
    const float* b0 = (const float*)d_in[3];
    const float* g0 = (const float*)d_in[4];
    const float* beta0 = (const float*)d_in[5];
    const float* W1 = (const float*)d_in[6];
    const float* b1 = (const float*)d_in[7];
    const float* g1 = (const float*)d_in[8];
    const float* beta1 = (const float*)d_in[9];
    const float* W2 = (const float*)d_in[10];
    const float* b2 = (const float*)d_in[11];
    const int* user_id = (const int*)d_in[12];
    const int* pos_item = (const int*)d_in[13];
    const int* neg_item = (const int*)d_in[14];
    const int* ei = (const int*)d_in[15];
    const int* src = ei;
    const int* dst = ei + NE;

    float* out = (float*)d_out;
    float* xout = out + 1;  // [rec_loss, x(150000x64)] -- only 4B aligned!

    const int EB4 = (NE / 4 + 255) / 256;
    const int AGGB = 2048;
    const int GB = (NN + 127) / 128;  // 1172
    const int W64 = 64 * 128 / 4, W128 = 128 * 128 / 4, W64b = 128 * 64 / 4;

    // setup + CSR build
    k_zero<<<(NN + 255) / 256, 256>>>();
    k_wconv<<<(W64 + 255) / 256, 256>>>(W0, W64, 0);
    k_wconv<<<(W128 + 255) / 256, 256>>>(W1, W128, 128 * 128);
    k_wconv<<<(W64b + 255) / 256, 256>>>(W2, W64b, 2 * 128 * 128);
    k_deg<<<EB4, 256>>>(dst);
    k_dis<<<(NN + 255) / 256, 256>>>();
    k_concat16<<<(NN * 8 + 255) / 256, 256>>>(user_emb, item_emb);
    k_scan1<<<SCAN_B, 256>>>();
    k_scan2<<<1, 1024>>>();
    k_scan3<<<SCAN_B + 1, 256>>>();
    k_csrfill<<<EB4, 256>>>(src, dst);

    // ---- layer 0: aggregate in x-space (64-wide), then GEMM + b0 + stats ----
    k_aggx64<<<AGGB, 256>>>();
    k_gemm0stats<<<GB, 256>>>(0, b0);
    k_bnapply<<<(NN + 7) / 8, 256>>>(g0, beta0, 0);

    // ---- layer 1: 128 -> 128 ----
    k_gemmh<128, 128><<<GB, 256>>>(128 * 128);
    k_agg<128, false><<<AGGB, 256>>>(b1, nullptr, 512);
    k_bnapply<<<(NN + 7) / 8, 256>>>(g1, beta1, 512);

    // ---- layer 2: 128 -> 64 ----
    k_gemmh<128, 64><<<GB, 256>>>(2 * 128 * 128);
    k_agg<64, true><<<AGGB, 256>>>(b2, xout, 0);

    // ---- loss ----
    k_loss<<<(NBATCH + 7) / 8, 256>>>(xout, user_id, pos_item, neg_item);
    k_wloss<<<1, 1>>>(out);
}

// round 16
// speedup vs baseline: 1.0321x; 1.0321x over previous
#include <cuda_runtime.h>
#include <cuda_bf16.h>
#include <cuda_fp16.h>
#include <mma.h>
#include <math.h>

using namespace nvcuda;

#define USER_NUM 100000
#define ITEM_NUM 50000
#define NN 150000
#define NE 2400000
#define NBATCH 4096
#define SCAN_B ((NN + 255) / 256)   // 586

// Scratch (device globals; allocation is forbidden).
__device__ uint4 g_x16raw[150016 * 128 / 8];   // x·dis fp16 (GEMM A / layer input)
__device__ uint4 g_h16raw[150016 * 128 / 8];   // GEMM output h, fp16
__device__ uint4 g_w16raw[3 * 128 * 128 / 8];  // W0|W1|W2 fp16
#define G_X16 (reinterpret_cast<__half*>(g_x16raw))
#define G_H16 (reinterpret_cast<__half*>(g_h16raw))
#define G_W16 (reinterpret_cast<__half*>(g_w16raw))
__device__ uint2 g_a16raw[150016 * 128 / 4];   // conv output (pre-BN), fp16
#define G_A16 (reinterpret_cast<__half*>(g_a16raw))
__device__ float g_dis[150016];                // rsqrt(1+deg)
__device__ int   g_degi[150016];
__device__ int   g_rows[150016 + 16];          // CSR row offsets (by dst)
__device__ int   g_cursor[150016];
__device__ int   g_part[1024];
__device__ int   g_csrc[NE];                   // CSR column (src) ids
__device__ float g_stats[1024];                // L0: sum@0 sq@128 | L1: sum@512 sq@640
__device__ float g_loss;
__device__ int   g_cnt;

// ---------------- fused setup: zero + all W fp16 conversions ----------------
__global__ void k_setup(const float* __restrict__ W0, const float* __restrict__ W1,
                        const float* __restrict__ W2) {
    int i = blockIdx.x * 256 + threadIdx.x;
    if (i < NN) g_degi[i] = 0;
    if (i < 256) { g_stats[i] = 0.f; g_stats[512 + i] = 0.f; }
    if (i == 0) { g_loss = 0.f; g_cnt = 0; }
    // W conversion: 8192 float4 total (W0:2048, W1:4096, W2:2048)
    if (i < 8192) {
        const float* src;
        int woff, j;
        if (i < 2048) { src = W0; j = i; woff = 0; }
        else if (i < 6144) { src = W1; j = i - 2048; woff = 128 * 128; }
        else { src = W2; j = i - 6144; woff = 2 * 128 * 128; }
        float4 v = ((const float4*)src)[j];
        __align__(8) __half2 h[2];
        h[0] = __floats2half2_rn(v.x, v.y);
        h[1] = __floats2half2_rn(v.z, v.w);
        *reinterpret_cast<uint2*>(G_W16 + woff + j * 4) =
            *reinterpret_cast<const uint2*>(h);
    }
}

__global__ void k_deg(const int* __restrict__ dst) {
    int i = blockIdx.x * 256 + threadIdx.x;
    if (i >= NE / 4) return;
    int4 d = ((const int4*)dst)[i];
    atomicAdd(&g_degi[d.x], 1);
    atomicAdd(&g_degi[d.y], 1);
    atomicAdd(&g_degi[d.z], 1);
    atomicAdd(&g_degi[d.w], 1);
}

// ---------------- scan1 + dis (fused) ----------------
__global__ void k_scan1dis() {
    __shared__ int s[256];
    int tid = threadIdx.x;
    int i = blockIdx.x * 256 + tid;
    int v = (i < NN) ? g_degi[i] : 0;
    if (i < NN) g_dis[i] = rsqrtf(1.f + (float)v);
    s[tid] = v;
    __syncthreads();
    for (int off = 1; off < 256; off <<= 1) {
        int t = (tid >= off) ? s[tid - off] : 0;
        __syncthreads();
        s[tid] += t;
        __syncthreads();
    }
    if (i < NN) g_rows[i] = s[tid] - v;
    if (tid == 255) g_part[blockIdx.x] = s[255];
}

__global__ void k_scan2() {  // 1 block, 1024 threads
    __shared__ int s[1024];
    int tid = threadIdx.x;
    int v = (tid < SCAN_B) ? g_part[tid] : 0;
    s[tid] = v;
    __syncthreads();
    for (int off = 1; off < 1024; off <<= 1) {
        int t = (tid >= off) ? s[tid - off] : 0;
        __syncthreads();
        s[tid] += t;
        __syncthreads();
    }
    if (tid < SCAN_B) g_part[tid] = s[tid] - v;
}

// ---------------- scan3 + concat16 (fused; independent work) ----------------
__global__ void k_scan3cat(const float* __restrict__ ue, const float* __restrict__ ie) {
    int i = blockIdx.x * 256 + threadIdx.x;
    // scan3 part
    if (i < NN) {
        int r = g_rows[i] + g_part[i >> 8];
        g_rows[i] = r;
        g_cursor[i] = r;
    }
    if (i == NN) g_rows[NN] = NE;
    // concat16 part: one uint4 (8 halves) per thread, K=64
    const int TT = NN * 8;
    if (i < TT) {
        int row = i >> 3;
        int col = (i & 7) * 8;
        float d = g_dis[row];
        const float* srcp = (row < USER_NUM) ? ue + (size_t)row * 64 + col
                                             : ie + (size_t)(row - USER_NUM) * 64 + col;
        float4 v0 = *(const float4*)srcp;
        float4 v1 = *(const float4*)(srcp + 4);
        __align__(16) __half2 h[4];
        h[0] = __floats2half2_rn(v0.x * d, v0.y * d);
        h[1] = __floats2half2_rn(v0.z * d, v0.w * d);
        h[2] = __floats2half2_rn(v1.x * d, v1.y * d);
        h[3] = __floats2half2_rn(v1.z * d, v1.w * d);
        *reinterpret_cast<uint4*>(G_X16 + (size_t)row * 64 + col) =
            *reinterpret_cast<const uint4*>(h);
    }
}

__global__ void k_csrfill(const int* __restrict__ src, const int* __restrict__ dst) {
    int i = blockIdx.x * 256 + threadIdx.x;
    if (i >= NE / 4) return;
    int4 s = ((const int4*)src)[i];
    int4 d = ((const int4*)dst)[i];
    g_csrc[atomicAdd(&g_cursor[d.x], 1)] = s.x;
    g_csrc[atomicAdd(&g_cursor[d.y], 1)] = s.y;
    g_csrc[atomicAdd(&g_cursor[d.z], 1)] = s.z;
    g_csrc[atomicAdd(&g_cursor[d.w], 1)] = s.w;
}

// ---------------- tensor-core GEMM: g_h16 = g_x16 @ W16 ----------------
template <int K, int N>
__global__ __launch_bounds__(256) void k_gemmh(int woff) {
    __shared__ __half Ws[K * N];
    __shared__ float scr[8][256];
    const int tid = threadIdx.x;
    const int wid = tid >> 5;
    const int lane = tid & 31;

    for (int i = tid; i < K * N / 8; i += 256)
        ((uint4*)Ws)[i] = ((const uint4*)(G_W16 + woff))[i];
    __syncthreads();

    const size_t rowbase = (size_t)blockIdx.x * 128 + wid * 16;
    const __half* A = G_X16 + rowbase * K;

    wmma::fragment<wmma::accumulator, 16, 16, 16, float> acc[N / 16];
#pragma unroll
    for (int j = 0; j < N / 16; j++) wmma::fill_fragment(acc[j], 0.f);

#pragma unroll
    for (int k0 = 0; k0 < K / 16; k0++) {
        wmma::fragment<wmma::matrix_a, 16, 16, 16, __half, wmma::row_major> a;
        wmma::load_matrix_sync(a, A + k0 * 16, K);
#pragma unroll
        for (int j = 0; j < N / 16; j++) {
            wmma::fragment<wmma::matrix_b, 16, 16, 16, __half, wmma::row_major> b;
            wmma::load_matrix_sync(b, Ws + k0 * 16 * N + j * 16, N);
            wmma::mma_sync(acc[j], a, b, acc[j]);
        }
    }

    __half* H = G_H16 + rowbase * N;
    const int r = lane >> 1;
    const int c0 = (lane & 1) * 8;
#pragma unroll
    for (int j = 0; j < N / 16; j++) {
        wmma::store_matrix_sync(scr[wid], acc[j], 16, wmma::mem_row_major);
        __syncwarp();
        __align__(16) __half2 h[4];
#pragma unroll
        for (int t = 0; t < 4; t++)
            h[t] = __floats2half2_rn(scr[wid][r * 16 + c0 + 2 * t],
                                     scr[wid][r * 16 + c0 + 2 * t + 1]);
        *reinterpret_cast<uint4*>(H + (size_t)r * N + j * 16 + c0) =
            *reinterpret_cast<const uint4*>(h);
        __syncwarp();
    }
}

// ---------------- CSR aggregation (warp-per-node, U=8, fused BN stats) ---------
template <int N, bool FINAL>
__global__ __launch_bounds__(256) void k_agg(const float* __restrict__ b,
                                             float* __restrict__ out, int sbase) {
    constexpr int VE = N / 32;
    const int lane = threadIdx.x & 31;
    const int warp = threadIdx.x >> 5;
    __shared__ float s_sum[128], s_sq[128];
    if constexpr (!FINAL) {
        if (threadIdx.x < 128) { s_sum[threadIdx.x] = 0.f; s_sq[threadIdx.x] = 0.f; }
        __syncthreads();
    }
    float bv[VE], tsum[VE], tsq[VE];
#pragma unroll
    for (int i = 0; i < VE; i++) { bv[i] = b[lane * VE + i]; tsum[i] = 0.f; tsq[i] = 0.f; }

    for (int node = blockIdx.x * 8 + warp; node < NN; node += gridDim.x * 8) {
        float acc[VE];
        if constexpr (VE == 4) {
            uint2 raw = *(const uint2*)(G_H16 + (size_t)node * N + lane * 4);
            float2 f0 = __half22float2(*reinterpret_cast<__half2*>(&raw.x));
            float2 f1 = __half22float2(*reinterpret_cast<__half2*>(&raw.y));
            acc[0] = f0.x; acc[1] = f0.y; acc[2] = f1.x; acc[3] = f1.y;
        } else {
            unsigned raw = *(const unsigned*)(G_H16 + (size_t)node * N + lane * 2);
            float2 f = __half22float2(*reinterpret_cast<__half2*>(&raw));
            acc[0] = f.x; acc[1] = f.y;
        }
        int beg = g_rows[node], end = g_rows[node + 1];
        int e = beg;
        for (; e + 8 <= end; e += 8) {
            int sid[8];
#pragma unroll
            for (int u = 0; u < 8; u++) sid[u] = g_csrc[e + u];
            if constexpr (VE == 4) {
                uint2 r[8];
#pragma unroll
                for (int u = 0; u < 8; u++)
                    r[u] = *(const uint2*)(G_H16 + (size_t)sid[u] * N + lane * 4);
#pragma unroll
                for (int u = 0; u < 8; u++) {
                    float2 f0 = __half22float2(*reinterpret_cast<__half2*>(&r[u].x));
                    float2 f1 = __half22float2(*reinterpret_cast<__half2*>(&r[u].y));
                    acc[0] += f0.x; acc[1] += f0.y; acc[2] += f1.x; acc[3] += f1.y;
                }
            } else {
                unsigned r[8];
#pragma unroll
                for (int u = 0; u < 8; u++)
                    r[u] = *(const unsigned*)(G_H16 + (size_t)sid[u] * N + lane * 2);
#pragma unroll
                for (int u = 0; u < 8; u++) {
                    float2 f = __half22float2(*reinterpret_cast<__half2*>(&r[u]));
                    acc[0] += f.x; acc[1] += f.y;
                }
            }
        }
        for (; e < end; e++) {
            int s0 = g_csrc[e];
            if constexpr (VE == 4) {
                uint2 r0 = *(const uint2*)(G_H16 + (size_t)s0 * N + lane * 4);
                float2 f0 = __half22float2(*reinterpret_cast<__half2*>(&r0.x));
                float2 f1 = __half22float2(*reinterpret_cast<__half2*>(&r0.y));
                acc[0] += f0.x; acc[1] += f0.y; acc[2] += f1.x; acc[3] += f1.y;
            } else {
                unsigned r0 = *(const unsigned*)(G_H16 + (size_t)s0 * N + lane * 2);
                float2 f = __half22float2(*reinterpret_cast<__half2*>(&r0));
                acc[0] += f.x; acc[1] += f.y;
            }
        }
        float dd = g_dis[node];
        float v[VE];
#pragma unroll
        for (int i = 0; i < VE; i++) {
            v[i] = fmaf(acc[i], dd, bv[i]);
            if constexpr (!FINAL) { tsum[i] += v[i]; tsq[i] += v[i] * v[i]; }
        }

        if constexpr (FINAL) {
            float* orow = out + (size_t)node * N + lane * VE;
#pragma unroll
            for (int i = 0; i < VE; i++) orow[i] = v[i];
        } else {
            __align__(8) __half2 h[2];
            h[0] = __floats2half2_rn(v[0], v[1]);
            h[1] = __floats2half2_rn(v[2], v[3]);
            *reinterpret_cast<uint2*>(G_A16 + (size_t)node * 128 + lane * 4) =
                *reinterpret_cast<const uint2*>(h);
        }
    }

    if constexpr (!FINAL) {
#pragma unroll
        for (int i = 0; i < VE; i++) {
            atomicAdd(&s_sum[lane * VE + i], tsum[i]);
            atomicAdd(&s_sq[lane * VE + i], tsq[i]);
        }
        __syncthreads();
        if (threadIdx.x < 128) {
            atomicAdd(&g_stats[sbase + threadIdx.x], s_sum[threadIdx.x]);
            atomicAdd(&g_stats[sbase + 128 + threadIdx.x], s_sq[threadIdx.x]);
        }
    }
}

// ---------------- BN apply + ReLU + L2 + fp16 (reads G_A16) --------------------
__global__ __launch_bounds__(256) void k_bnapply(const float* __restrict__ g,
                                                 const float* __restrict__ beta,
                                                 int sbase) {
    __shared__ float s_sc[128], s_sh[128];
    if (threadIdx.x < 128) {
        int c = threadIdx.x;
        float m = g_stats[sbase + c] * (1.f / NN);
        float var = g_stats[sbase + 128 + c] * (1.f / NN) - m * m;
        float sc = g[c] * rsqrtf(var + 1e-5f);
        s_sc[c] = sc;
        s_sh[c] = beta[c] - m * sc;
    }
    __syncthreads();
    int row = blockIdx.x * 8 + (threadIdx.x >> 5);
    int lane = threadIdx.x & 31;
    if (row >= NN) return;
    uint2 raw = *reinterpret_cast<const uint2*>(G_A16 + (size_t)row * 128 + lane * 4);
    float2 f0 = __half22float2(*reinterpret_cast<__half2*>(&raw.x));
    float2 f1 = __half22float2(*reinterpret_cast<__half2*>(&raw.y));
    float4 sc = *reinterpret_cast<const float4*>(s_sc + lane * 4);
    float4 sh = *reinterpret_cast<const float4*>(s_sh + lane * 4);
    float y0 = fmaxf(fmaf(f0.x, sc.x, sh.x), 0.f);
    float y1 = fmaxf(fmaf(f0.y, sc.y, sh.y), 0.f);
    float y2 = fmaxf(fmaf(f1.x, sc.z, sh.z), 0.f);
    float y3 = fmaxf(fmaf(f1.y, sc.w, sh.w), 0.f);
    float sq = y0 * y0 + y1 * y1 + y2 * y2 + y3 * y3;
#pragma unroll
    for (int o = 16; o; o >>= 1) sq += __shfl_xor_sync(0xffffffffu, sq, o);
    float inv = 1.f / fmaxf(sqrtf(sq), 1e-12f);
    inv *= g_dis[row];  // pre-scale for next GEMM
    __align__(8) __half2 h[2];
    h[0] = __floats2half2_rn(y0 * inv, y1 * inv);
    h[1] = __floats2half2_rn(y2 * inv, y3 * inv);
    *reinterpret_cast<uint2*>(G_X16 + (size_t)row * 128 + lane * 4) =
        *reinterpret_cast<const uint2*>(h);
}

// ---------------- BPR loss (fused finalize via counter) ----------------
#define LOSS_B ((NBATCH + 7) / 8)
__global__ __launch_bounds__(256) void k_loss(const float* __restrict__ xo,
                                              const int* __restrict__ uid,
                                              const int* __restrict__ pid,
                                              const int* __restrict__ nid,
                                              float* __restrict__ out) {
    int s = blockIdx.x * 8 + (threadIdx.x >> 5);
    int lane = threadIdx.x & 31;
    if (s < NBATCH) {
        const float* u = xo + (size_t)uid[s] * 64;
        const float* p = xo + (size_t)(USER_NUM + pid[s]) * 64;
        const float* nr = xo + (size_t)(USER_NUM + nid[s]) * 64;
        float ps = 0.f, ns = 0.f;
#pragma unroll
        for (int j = 0; j < 2; j++) {
            int c = lane + j * 32;
            float uv = u[c];
            ps += uv * p[c];
            ns += uv * nr[c];
        }
#pragma unroll
        for (int o = 16; o; o >>= 1) {
            ps += __shfl_xor_sync(0xffffffffu, ps, o);
            ns += __shfl_xor_sync(0xffffffffu, ns, o);
        }
        if (lane == 0) {
            float z = ps - ns;
            float ls = fminf(z, 0.f) - log1pf(expf(-fabsf(z)));
            atomicAdd(&g_loss, ls);
        }
    }
    __syncthreads();
    if (threadIdx.x == 0) {
        __threadfence();
        int old = atomicAdd(&g_cnt, 1);
        if (old == gridDim.x - 1) {
            out[0] = -g_loss * (1.f / NBATCH);
        }
    }
}

// ---------------- launch ----------------
extern "C" void kernel_launch(void* const* d_in, const int* in_sizes, int n_in,
                              void* d_out, int out_size) {
    const float* user_emb = (const float*)d_in[0];
    const float* item_emb = (const float*)d_in[1];
    const float* W0 = (const float*)d_in[2];
    const float* b0 = (const float*)d_in[3];
    const float* g0 = (const float*)d_in[4];
    const float* beta0 = (const float*)d_in[5];
    const float* W1 = (const float*)d_in[6];
    const float* b1 = (const float*)d_in[7];
    const float* g1 = (const float*)d_in[8];
    const float* beta1 = (const float*)d_in[9];
    const float* W2 = (const float*)d_in[10];
    const float* b2 = (const float*)d_in[11];
    const int* user_id = (const int*)d_in[12];
    const int* pos_item = (const int*)d_in[13];
    const int* neg_item = (const int*)d_in[14];
    const int* ei = (const int*)d_in[15];
    const int* src = ei;
    const int* dst = ei + NE;

    float* out = (float*)d_out;
    float* xout = out + 1;  // [rec_loss, x(150000x64)] -- only 4B aligned!

    const int EB4 = (NE / 4 + 255) / 256;
    const int AGGB = 1184;            // 148 SMs x 8 blocks
    const int GB = (NN + 127) / 128;  // 1172
    const int CATB = (NN * 8 + 255) / 256;

    // setup + CSR build (15 launches total)
    k_setup<<<(NN + 255) / 256, 256>>>(W0, W1, W2);
    k_deg<<<EB4, 256>>>(dst);
    k_scan1dis<<<SCAN_B, 256>>>();
    k_scan2<<<1, 1024>>>();
    k_scan3cat<<<CATB, 256>>>(user_emb, item_emb);
    k_csrfill<<<EB4, 256>>>(src, dst);

    // ---- layer 0: 64 -> 128 ----
    k_gemmh<64, 128><<<GB, 256>>>(0);
    k_agg<128, false><<<AGGB, 256>>>(b0, nullptr, 0);
    k_bnapply<<<(NN + 7) / 8, 256>>>(g0, beta0, 0);

    // ---- layer 1: 128 -> 128 ----
    k_gemmh<128, 128><<<GB, 256>>>(128 * 128);
    k_agg<128, false><<<AGGB, 256>>>(b1, nullptr, 512);
    k_bnapply<<<(NN + 7) / 8, 256>>>(g1, beta1, 512);

    // ---- layer 2: 128 -> 64 ----
    k_gemmh<128, 64><<<GB, 256>>>(2 * 128 * 128);
    k_agg<64, true><<<AGGB, 256>>>(b2, xout, 0);

    // ---- loss (fused finalize) ----
    k_loss<<<LOSS_B, 256>>>(xout, user_id, pos_item, neg_item, out);
}

// round 17
// speedup vs baseline: 1.0525x; 1.0198x over previous
#include <cuda_runtime.h>
#include <cuda_bf16.h>
#include <cuda_fp16.h>
#include <mma.h>
#include <math.h>

using namespace nvcuda;

#define USER_NUM 100000
#define ITEM_NUM 50000
#define NN 150000
#define NE 2400000
#define NBATCH 4096
#define SCAN_B ((NN + 255) / 256)   // 586

// Scratch (device globals; allocation is forbidden).
__device__ uint4 g_x16raw[150016 * 128 / 8];   // x·dis fp16 (GEMM A / layer input)
__device__ uint4 g_h16raw[150016 * 128 / 8];   // GEMM output h, fp16
__device__ uint4 g_w16raw[3 * 128 * 128 / 8];  // W0|W1|W2 fp16
#define G_X16 (reinterpret_cast<__half*>(g_x16raw))
#define G_H16 (reinterpret_cast<__half*>(g_h16raw))
#define G_W16 (reinterpret_cast<__half*>(g_w16raw))
__device__ uint2 g_a16raw[150016 * 128 / 4];   // conv output (pre-BN), fp16
#define G_A16 (reinterpret_cast<__half*>(g_a16raw))
__device__ float g_dis[150016];                // rsqrt(1+deg)
__device__ int   g_degi[150016];
__device__ int   g_rows[150016 + 16];          // CSR row offsets (by dst)
__device__ int   g_cursor[150016];
__device__ int   g_part[1024];
__device__ int   g_csrc[NE];                   // CSR column (src) ids
__device__ float g_stats[1024];                // L0: sum@0 sq@128 | L1: sum@512 sq@640
__device__ float g_loss;
__device__ int   g_cnt;

__device__ __forceinline__ __half2 H2(unsigned u) {
    return *reinterpret_cast<__half2*>(&u);
}

// ---------------- fused setup: zero + all W fp16 conversions ----------------
__global__ void k_setup(const float* __restrict__ W0, const float* __restrict__ W1,
                        const float* __restrict__ W2) {
    int i = blockIdx.x * 256 + threadIdx.x;
    if (i < NN) g_degi[i] = 0;
    if (i < 256) { g_stats[i] = 0.f; g_stats[512 + i] = 0.f; }
    if (i == 0) { g_loss = 0.f; g_cnt = 0; }
    if (i < 8192) {
        const float* src;
        int woff, j;
        if (i < 2048) { src = W0; j = i; woff = 0; }
        else if (i < 6144) { src = W1; j = i - 2048; woff = 128 * 128; }
        else { src = W2; j = i - 6144; woff = 2 * 128 * 128; }
        float4 v = ((const float4*)src)[j];
        __align__(8) __half2 h[2];
        h[0] = __floats2half2_rn(v.x, v.y);
        h[1] = __floats2half2_rn(v.z, v.w);
        *reinterpret_cast<uint2*>(G_W16 + woff + j * 4) =
            *reinterpret_cast<const uint2*>(h);
    }
}

__global__ void k_deg(const int* __restrict__ dst) {
    int i = blockIdx.x * 256 + threadIdx.x;
    if (i >= NE / 4) return;
    int4 d = ((const int4*)dst)[i];
    atomicAdd(&g_degi[d.x], 1);
    atomicAdd(&g_degi[d.y], 1);
    atomicAdd(&g_degi[d.z], 1);
    atomicAdd(&g_degi[d.w], 1);
}

// ---------------- scan1 + dis (fused) ----------------
__global__ void k_scan1dis() {
    __shared__ int s[256];
    int tid = threadIdx.x;
    int i = blockIdx.x * 256 + tid;
    int v = (i < NN) ? g_degi[i] : 0;
    if (i < NN) g_dis[i] = rsqrtf(1.f + (float)v);
    s[tid] = v;
    __syncthreads();
    for (int off = 1; off < 256; off <<= 1) {
        int t = (tid >= off) ? s[tid - off] : 0;
        __syncthreads();
        s[tid] += t;
        __syncthreads();
    }
    if (i < NN) g_rows[i] = s[tid] - v;
    if (tid == 255) g_part[blockIdx.x] = s[255];
}

__global__ void k_scan2() {  // 1 block, 1024 threads
    __shared__ int s[1024];
    int tid = threadIdx.x;
    int v = (tid < SCAN_B) ? g_part[tid] : 0;
    s[tid] = v;
    __syncthreads();
    for (int off = 1; off < 1024; off <<= 1) {
        int t = (tid >= off) ? s[tid - off] : 0;
        __syncthreads();
        s[tid] += t;
        __syncthreads();
    }
    if (tid < SCAN_B) g_part[tid] = s[tid] - v;
}

// ---------------- scan3 + concat16 (fused; independent work) ----------------
__global__ void k_scan3cat(const float* __restrict__ ue, const float* __restrict__ ie) {
    int i = blockIdx.x * 256 + threadIdx.x;
    if (i < NN) {
        int r = g_rows[i] + g_part[i >> 8];
        g_rows[i] = r;
        g_cursor[i] = r;
    }
    if (i == NN) g_rows[NN] = NE;
    const int TT = NN * 8;
    if (i < TT) {
        int row = i >> 3;
        int col = (i & 7) * 8;
        float d = g_dis[row];
        const float* srcp = (row < USER_NUM) ? ue + (size_t)row * 64 + col
                                             : ie + (size_t)(row - USER_NUM) * 64 + col;
        float4 v0 = *(const float4*)srcp;
        float4 v1 = *(const float4*)(srcp + 4);
        __align__(16) __half2 h[4];
        h[0] = __floats2half2_rn(v0.x * d, v0.y * d);
        h[1] = __floats2half2_rn(v0.z * d, v0.w * d);
        h[2] = __floats2half2_rn(v1.x * d, v1.y * d);
        h[3] = __floats2half2_rn(v1.z * d, v1.w * d);
        *reinterpret_cast<uint4*>(G_X16 + (size_t)row * 64 + col) =
            *reinterpret_cast<const uint4*>(h);
    }
}

__global__ void k_csrfill(const int* __restrict__ src, const int* __restrict__ dst) {
    int i = blockIdx.x * 256 + threadIdx.x;
    if (i >= NE / 4) return;
    int4 s = ((const int4*)src)[i];
    int4 d = ((const int4*)dst)[i];
    g_csrc[atomicAdd(&g_cursor[d.x], 1)] = s.x;
    g_csrc[atomicAdd(&g_cursor[d.y], 1)] = s.y;
    g_csrc[atomicAdd(&g_cursor[d.z], 1)] = s.z;
    g_csrc[atomicAdd(&g_cursor[d.w], 1)] = s.w;
}

// ---------------- tensor-core GEMM: g_h16 = g_x16 @ W16 ----------------
template <int K, int N>
__global__ __launch_bounds__(256) void k_gemmh(int woff) {
    __shared__ __half Ws[K * N];
    __shared__ float scr[8][256];
    const int tid = threadIdx.x;
    const int wid = tid >> 5;
    const int lane = tid & 31;

    for (int i = tid; i < K * N / 8; i += 256)
        ((uint4*)Ws)[i] = ((const uint4*)(G_W16 + woff))[i];
    __syncthreads();

    const size_t rowbase = (size_t)blockIdx.x * 128 + wid * 16;
    const __half* A = G_X16 + rowbase * K;

    wmma::fragment<wmma::accumulator, 16, 16, 16, float> acc[N / 16];
#pragma unroll
    for (int j = 0; j < N / 16; j++) wmma::fill_fragment(acc[j], 0.f);

#pragma unroll
    for (int k0 = 0; k0 < K / 16; k0++) {
        wmma::fragment<wmma::matrix_a, 16, 16, 16, __half, wmma::row_major> a;
        wmma::load_matrix_sync(a, A + k0 * 16, K);
#pragma unroll
        for (int j = 0; j < N / 16; j++) {
            wmma::fragment<wmma::matrix_b, 16, 16, 16, __half, wmma::row_major> b;
            wmma::load_matrix_sync(b, Ws + k0 * 16 * N + j * 16, N);
            wmma::mma_sync(acc[j], a, b, acc[j]);
        }
    }

    __half* H = G_H16 + rowbase * N;
    const int r = lane >> 1;
    const int c0 = (lane & 1) * 8;
#pragma unroll
    for (int j = 0; j < N / 16; j++) {
        wmma::store_matrix_sync(scr[wid], acc[j], 16, wmma::mem_row_major);
        __syncwarp();
        __align__(16) __half2 h[4];
#pragma unroll
        for (int t = 0; t < 4; t++)
            h[t] = __floats2half2_rn(scr[wid][r * 16 + c0 + 2 * t],
                                     scr[wid][r * 16 + c0 + 2 * t + 1]);
        *reinterpret_cast<uint4*>(H + (size_t)r * N + j * 16 + c0) =
            *reinterpret_cast<const uint4*>(h);
        __syncwarp();
    }
}

// ---------------- CSR aggregation (warp-per-node, U=8, HADD2 tree) -------------
// v[n] = dis[n]*(h[n] + sum h[src]) + b; 8-edge blocks summed pairwise in fp16
// (depth-2 tree), partial sums accumulated in fp32.
template <int N, bool FINAL>
__global__ __launch_bounds__(256) void k_agg(const float* __restrict__ b,
                                             float* __restrict__ out, int sbase) {
    constexpr int VE = N / 32;
    const int lane = threadIdx.x & 31;
    const int warp = threadIdx.x >> 5;
    __shared__ float s_sum[128], s_sq[128];
    if constexpr (!FINAL) {
        if (threadIdx.x < 128) { s_sum[threadIdx.x] = 0.f; s_sq[threadIdx.x] = 0.f; }
        __syncthreads();
    }
    float bv[VE], tsum[VE], tsq[VE];
#pragma unroll
    for (int i = 0; i < VE; i++) { bv[i] = b[lane * VE + i]; tsum[i] = 0.f; tsq[i] = 0.f; }

    for (int node = blockIdx.x * 8 + warp; node < NN; node += gridDim.x * 8) {
        float acc[VE];
        if constexpr (VE == 4) {
            uint2 raw = *(const uint2*)(G_H16 + (size_t)node * N + lane * 4);
            float2 f0 = __half22float2(H2(raw.x));
            float2 f1 = __half22float2(H2(raw.y));
            acc[0] = f0.x; acc[1] = f0.y; acc[2] = f1.x; acc[3] = f1.y;
        } else {
            unsigned raw = *(const unsigned*)(G_H16 + (size_t)node * N + lane * 2);
            float2 f = __half22float2(H2(raw));
            acc[0] = f.x; acc[1] = f.y;
        }
        int beg = g_rows[node], end = g_rows[node + 1];
        int e = beg;
        for (; e + 8 <= end; e += 8) {
            int sid[8];
#pragma unroll
            for (int u = 0; u < 8; u++) sid[u] = g_csrc[e + u];
            if constexpr (VE == 4) {
                uint2 r[8];
#pragma unroll
                for (int u = 0; u < 8; u++)
                    r[u] = *(const uint2*)(G_H16 + (size_t)sid[u] * N + lane * 4);
                // depth-2 fp16 tree per half2 slot: q = (r0+r1)+(r2+r3), (r4+r5)+(r6+r7)
                __half2 q0x = __hadd2(__hadd2(H2(r[0].x), H2(r[1].x)),
                                      __hadd2(H2(r[2].x), H2(r[3].x)));
                __half2 q1x = __hadd2(__hadd2(H2(r[4].x), H2(r[5].x)),
                                      __hadd2(H2(r[6].x), H2(r[7].x)));
                __half2 q0y = __hadd2(__hadd2(H2(r[0].y), H2(r[1].y)),
                                      __hadd2(H2(r[2].y), H2(r[3].y)));
                __half2 q1y = __hadd2(__hadd2(H2(r[4].y), H2(r[5].y)),
                                      __hadd2(H2(r[6].y), H2(r[7].y)));
                float2 f0 = __half22float2(q0x);
                float2 f1 = __half22float2(q1x);
                float2 f2 = __half22float2(q0y);
                float2 f3 = __half22float2(q1y);
                acc[0] += f0.x + f1.x; acc[1] += f0.y + f1.y;
                acc[2] += f2.x + f3.x; acc[3] += f2.y + f3.y;
            } else {
                unsigned r[8];
#pragma unroll
                for (int u = 0; u < 8; u++)
                    r[u] = *(const unsigned*)(G_H16 + (size_t)sid[u] * N + lane * 2);
                __half2 q0 = __hadd2(__hadd2(H2(r[0]), H2(r[1])),
                                     __hadd2(H2(r[2]), H2(r[3])));
                __half2 q1 = __hadd2(__hadd2(H2(r[4]), H2(r[5])),
                                     __hadd2(H2(r[6]), H2(r[7])));
                float2 f0 = __half22float2(q0);
                float2 f1 = __half22float2(q1);
                acc[0] += f0.x + f1.x;
                acc[1] += f0.y + f1.y;
            }
        }
        for (; e < end; e++) {
            int s0 = g_csrc[e];
            if constexpr (VE == 4) {
                uint2 r0 = *(const uint2*)(G_H16 + (size_t)s0 * N + lane * 4);
                float2 f0 = __half22float2(H2(r0.x));
                float2 f1 = __half22float2(H2(r0.y));
                acc[0] += f0.x; acc[1] += f0.y; acc[2] += f1.x; acc[3] += f1.y;
            } else {
                unsigned r0 = *(const unsigned*)(G_H16 + (size_t)s0 * N + lane * 2);
                float2 f = __half22float2(H2(r0));
                acc[0] += f.x; acc[1] += f.y;
            }
        }
        float dd = g_dis[node];
        float v[VE];
#pragma unroll
        for (int i = 0; i < VE; i++) {
            v[i] = fmaf(acc[i], dd, bv[i]);
            if constexpr (!FINAL) { tsum[i] += v[i]; tsq[i] += v[i] * v[i]; }
        }

        if constexpr (FINAL) {
            float* orow = out + (size_t)node * N + lane * VE;
#pragma unroll
            for (int i = 0; i < VE; i++) orow[i] = v[i];
        } else {
            __align__(8) __half2 h[2];
            h[0] = __floats2half2_rn(v[0], v[1]);
            h[1] = __floats2half2_rn(v[2], v[3]);
            *reinterpret_cast<uint2*>(G_A16 + (size_t)node * 128 + lane * 4) =
                *reinterpret_cast<const uint2*>(h);
        }
    }

    if constexpr (!FINAL) {
#pragma unroll
        for (int i = 0; i < VE; i++) {
            atomicAdd(&s_sum[lane * VE + i], tsum[i]);
            atomicAdd(&s_sq[lane * VE + i], tsq[i]);
        }
        __syncthreads();
        if (threadIdx.x < 128) {
            atomicAdd(&g_stats[sbase + threadIdx.x], s_sum[threadIdx.x]);
            atomicAdd(&g_stats[sbase + 128 + threadIdx.x], s_sq[threadIdx.x]);
        }
    }
}

// ---------------- BN apply + ReLU + L2 + fp16 (reads G_A16) --------------------
__global__ __launch_bounds__(256) void k_bnapply(const float* __restrict__ g,
                                                 const float* __restrict__ beta,
                                                 int sbase) {
    __shared__ float s_sc[128], s_sh[128];
    if (threadIdx.x < 128) {
        int c = threadIdx.x;
        float m = g_stats[sbase + c] * (1.f / NN);
        float var = g_stats[sbase + 128 + c] * (1.f / NN) - m * m;
        float sc = g[c] * rsqrtf(var + 1e-5f);
        s_sc[c] = sc;
        s_sh[c] = beta[c] - m * sc;
    }
    __syncthreads();
    int row = blockIdx.x * 8 + (threadIdx.x >> 5);
    int lane = threadIdx.x & 31;
    if (row >= NN) return;
    uint2 raw = *reinterpret_cast<const uint2*>(G_A16 + (size_t)row * 128 + lane * 4);
    float2 f0 = __half22float2(H2(raw.x));
    float2 f1 = __half22float2(H2(raw.y));
    float4 sc = *reinterpret_cast<const float4*>(s_sc + lane * 4);
    float4 sh = *reinterpret_cast<const float4*>(s_sh + lane * 4);
    float y0 = fmaxf(fmaf(f0.x, sc.x, sh.x), 0.f);
    float y1 = fmaxf(fmaf(f0.y, sc.y, sh.y), 0.f);
    float y2 = fmaxf(fmaf(f1.x, sc.z, sh.z), 0.f);
    float y3 = fmaxf(fmaf(f1.y, sc.w, sh.w), 0.f);
    float sq = y0 * y0 + y1 * y1 + y2 * y2 + y3 * y3;
#pragma unroll
    for (int o = 16; o; o >>= 1) sq += __shfl_xor_sync(0xffffffffu, sq, o);
    float inv = 1.f / fmaxf(sqrtf(sq), 1e-12f);
    inv *= g_dis[row];  // pre-scale for next GEMM
    __align__(8) __half2 h[2];
    h[0] = __floats2half2_rn(y0 * inv, y1 * inv);
    h[1] = __floats2half2_rn(y2 * inv, y3 * inv);
    *reinterpret_cast<uint2*>(G_X16 + (size_t)row * 128 + lane * 4) =
        *reinterpret_cast<const uint2*>(h);
}

// ---------------- BPR loss (fused finalize via counter) ----------------
#define LOSS_B ((NBATCH + 7) / 8)
__global__ __launch_bounds__(256) void k_loss(const float* __restrict__ xo,
                                              const int* __restrict__ uid,
                                              const int* __restrict__ pid,
                                              const int* __restrict__ nid,
                                              float* __restrict__ out) {
    int s = blockIdx.x * 8 + (threadIdx.x >> 5);
    int lane = threadIdx.x & 31;
    if (s < NBATCH) {
        const float* u = xo + (size_t)uid[s] * 64;
        const float* p = xo + (size_t)(USER_NUM + pid[s]) * 64;
        const float* nr = xo + (size_t)(USER_NUM + nid[s]) * 64;
        float ps = 0.f, ns = 0.f;
#pragma unroll
        for (int j = 0; j < 2; j++) {
            int c = lane + j * 32;
            float uv = u[c];
            ps += uv * p[c];
            ns += uv * nr[c];
        }
#pragma unroll
        for (int o = 16; o; o >>= 1) {
            ps += __shfl_xor_sync(0xffffffffu, ps, o);
            ns += __shfl_xor_sync(0xffffffffu, ns, o);
        }
        if (lane == 0) {
            float z = ps - ns;
            float ls = fminf(z, 0.f) - log1pf(expf(-fabsf(z)));
            atomicAdd(&g_loss, ls);
        }
    }
    __syncthreads();
    if (threadIdx.x == 0) {
        __threadfence();
        int old = atomicAdd(&g_cnt, 1);
        if (old == gridDim.x - 1) {
            out[0] = -g_loss * (1.f / NBATCH);
        }
    }
}

// ---------------- launch ----------------
extern "C" void kernel_launch(void* const* d_in, const int* in_sizes, int n_in,
                              void* d_out, int out_size) {
    const float* user_emb = (const float*)d_in[0];
    const float* item_emb = (const float*)d_in[1];
    const float* W0 = (const float*)d_in[2];
    const float* b0 = (const float*)d_in[3];
    const float* g0 = (const float*)d_in[4];
    const float* beta0 = (const float*)d_in[5];
    const float* W1 = (const float*)d_in[6];
    const float* b1 = (const float*)d_in[7];
    const float* g1 = (const float*)d_in[8];
    const float* beta1 = (const float*)d_in[9];
    const float* W2 = (const float*)d_in[10];
    const float* b2 = (const float*)d_in[11];
    const int* user_id = (const int*)d_in[12];
    const int* pos_item = (const int*)d_in[13];
    const int* neg_item = (const int*)d_in[14];
    const int* ei = (const int*)d_in[15];
    const int* src = ei;
    const int* dst = ei + NE;

    float* out = (float*)d_out;
    float* xout = out + 1;  // [rec_loss, x(150000x64)] -- only 4B aligned!

    const int EB4 = (NE / 4 + 255) / 256;
    const int AGGB = 1184;            // 148 SMs x 8 blocks
    const int GB = (NN + 127) / 128;  // 1172
    const int CATB = (NN * 8 + 255) / 256;

    // setup + CSR build
    k_setup<<<(NN + 255) / 256, 256>>>(W0, W1, W2);
    k_deg<<<EB4, 256>>>(dst);
    k_scan1dis<<<SCAN_B, 256>>>();
    k_scan2<<<1, 1024>>>();
    k_scan3cat<<<CATB, 256>>>(user_emb, item_emb);
    k_csrfill<<<EB4, 256>>>(src, dst);

    // ---- layer 0: 64 -> 128 ----
    k_gemmh<64, 128><<<GB, 256>>>(0);
    k_agg<128, false><<<AGGB, 256>>>(b0, nullptr, 0);
    k_bnapply<<<(NN + 7) / 8, 256>>>(g0, beta0, 0);

    // ---- layer 1: 128 -> 128 ----
    k_gemmh<128, 128><<<GB, 256>>>(128 * 128);
    k_agg<128, false><<<AGGB, 256>>>(b1, nullptr, 512);
    k_bnapply<<<(NN + 7) / 8, 256>>>(g1, beta1, 512);

    // ---- layer 2: 128 -> 64 ----
    k_gemmh<128, 64><<<GB, 256>>>(2 * 128 * 128);
    k_agg<64, true><<<AGGB, 256>>>(b2, xout, 0);

    // ---- loss (fused finalize) ----
    k_loss<<<LOSS_B, 256>>>(xout, user_id, pos_item, neg_item, out);
}